// round 4
// baseline (speedup 1.0000x reference)
#include <cuda_runtime.h>
#include <math.h>

#define BB 64
#define TT 256
#define FF 64
#define UU 512
#define GG 2048      // 4*UU
#define NBLK 128
#define NTHR 256
#define CU 4         // units per block
#define NC 16        // gate-columns per block (4 gates x 4 units)
#define KT 128       // k-chunk for h staging
#define WS 513       // rec weight row stride in float2 (odd -> conflict-free)
#define WXS 65       // x weight row stride in float2

// ---- static device scratch (no cudaMalloc anywhere) ----
__device__ float g_hsT[(size_t)TT * UU * BB]; // all h: [(t*512+u)*64 + b]
__device__ float g_coef[TT];
__device__ float g_shift[TT];
__device__ float g_sumW;
__device__ unsigned g_cnt = 0;
__device__ volatile unsigned g_gen = 0;       // monotonic across launches

__device__ __forceinline__ float sigmoidf_(float x) { return 1.f / (1.f + expf(-x)); }

// packed fp32x2 FMA (Blackwell): d = a*b + c on two fp32 lanes of a 64-bit reg
__device__ __forceinline__ unsigned long long fma2(unsigned long long a,
                                                   unsigned long long b,
                                                   unsigned long long c) {
    unsigned long long d;
    asm("fma.rn.f32x2 %0, %1, %2, %3;" : "=l"(d) : "l"(a), "l"(b), "l"(c));
    return d;
}
__device__ __forceinline__ unsigned long long pack2(float v) {
    unsigned long long p;
    unsigned u = __float_as_uint(v);
    asm("mov.b64 %0, {%1, %1};" : "=l"(p) : "r"(u));
    return p;
}

__device__ __forceinline__ void cp_async16(float* smem_dst, const void* gmem_src) {
    unsigned s = (unsigned)__cvta_generic_to_shared(smem_dst);
    asm volatile("cp.async.cg.shared.global [%0], [%1], 16;\n" :: "r"(s), "l"(gmem_src));
}
#define CP_COMMIT() asm volatile("cp.async.commit_group;\n" ::: "memory")
#define CP_WAIT1()  asm volatile("cp.async.wait_group 1;\n" ::: "memory")
#define CP_WAIT0()  asm volatile("cp.async.wait_group 0;\n" ::: "memory")

__device__ __forceinline__ void grid_barrier() {
    __threadfence();
    __syncthreads();
    if (threadIdx.x == 0) {
        unsigned gen = g_gen;
        if (atomicAdd(&g_cnt, 1u) == (unsigned)(NBLK - 1)) {
            g_cnt = 0u;
            __threadfence();
            g_gen = gen + 1u;
        } else {
            while (g_gen == gen) { }
        }
    }
    __syncthreads();
}

// ---------------------------------------------------------------------------
// prep (parallel): block t<TT computes coef/shift; block TT reduces out_W.
// ---------------------------------------------------------------------------
__global__ void prep_kernel(const float* __restrict__ attW,
                            const float* __restrict__ attb,
                            const float* __restrict__ outW)
{
    __shared__ float red[256];
    int tid = threadIdx.x;
    if (blockIdx.x < TT) {
        int t = blockIdx.x;
        float s = 0.f;
        for (int j = tid; j < t; j += 256) s += attW[t * TT + j];
        red[tid] = s;
        __syncthreads();
        for (int off = 128; off > 0; off >>= 1) {
            if (tid < off) red[tid] += red[tid + off];
            __syncthreads();
        }
        if (tid == 0) {
            g_coef[t]  = (t == 0) ? 1.f : red[0];
            g_shift[t] = (t == 0) ? 0.f : attb[t];
        }
    } else {
        red[tid] = outW[tid] + outW[tid + 256];
        __syncthreads();
        for (int off = 128; off > 0; off >>= 1) {
            if (tid < off) red[tid] += red[tid + off];
            __syncthreads();
        }
        if (tid == 0) g_sumW = red[0];
    }
}

// ---------------------------------------------------------------------------
// Persistent LSTM. 128 blocks, 256 threads (2 warps/SMSP).
// Block owns 4 units (16 gate cols). Thread GEMM tile: 1 col x 4 batches.
// Weights stored duplicated (f32x2) in smem -> inner loop is pure
// {LDS.64 w, LDS.128 h, 2x FFMA2} with zero packing MOVs.
// ---------------------------------------------------------------------------
// smem (floats):
//   sh   [2][KT*64]       = 16384
//   sWd  [16][513 f32x2]  = 16416
//   sWxd [16][65 f32x2]   =  2080
//   sx2  [64][64]         =  4096
//   sg   [16][68]         =  1088
#define OFF_SH   0
#define OFF_SW   (2 * KT * BB)
#define OFF_SWX  (OFF_SW + NC * WS * 2)
#define OFF_SX   (OFF_SWX + NC * WXS * 2)
#define OFF_SG   (OFF_SX + FF * BB)
#define SMEM_FLOATS (OFF_SG + NC * 68)

__global__ void __launch_bounds__(NTHR, 1)
lstm_persist(const float* __restrict__ x,     // (B,T,F)
             const float* __restrict__ Wk,    // (F,4U)
             const float* __restrict__ Rk,    // (U,4U)
             const float* __restrict__ bias)  // (4U)
{
    extern __shared__ float smem[];
    float* sh   = smem + OFF_SH;
    float* sWd  = smem + OFF_SW;    // float2-dup rec weights, row stride WS f2
    float* sWxd = smem + OFF_SWX;   // float2-dup input weights, stride WXS f2
    float* sx2  = smem + OFF_SX;    // x_t transposed [f][b]
    float* sg   = smem + OFF_SG;    // gate exchange [c][b], stride 68

    const int tid = threadIdx.x;
    const int bid = blockIdx.x;
    const int u0  = bid * CU;

    // ---- one-time weight staging, duplicated halves ----
    for (int idx = tid; idx < UU * NC; idx += NTHR) {
        int k = idx >> 4, c = idx & 15;
        int gcol = (c >> 2) * UU + u0 + (c & 3);
        float w = Rk[(size_t)k * GG + gcol];
        ((float2*)sWd)[c * WS + k] = make_float2(w, w);
    }
    for (int idx = tid; idx < FF * NC; idx += NTHR) {
        int f = idx >> 4, c = idx & 15;
        int gcol = (c >> 2) * UU + u0 + (c & 3);
        float w = Wk[(size_t)f * GG + gcol];
        ((float2*)sWxd)[c * WXS + f] = make_float2(w, w);
    }

    // GEMM identity: col c (0..15), batches [b0, b0+4)
    const int c  = tid & 15;
    const int b0 = (tid >> 4) << 2;
    const unsigned long long bp = pack2(bias[(c >> 2) * UU + u0 + (c & 3)]);

    // pointwise identity: unit pj (0..3), batch pb (0..63)
    const int pj = tid >> 6;
    const int pb = tid & 63;
    float creg = 0.f;

    const unsigned long long* wrow  = (const unsigned long long*)((float2*)sWd  + c * WS);
    const unsigned long long* wxrow = (const unsigned long long*)((float2*)sWxd + c * WXS);

    __syncthreads();

    for (int t = 0; t < TT; ++t) {
        // ---- stage x_t transposed: sx2[f*64 + b] ----
        for (int i = tid; i < (BB * FF) / 4; i += NTHR) {
            int b  = i & 63;
            int f0 = (i >> 6) << 2;
            float4 xv = *(const float4*)(x + ((size_t)b * TT + t) * FF + f0);
            sx2[(f0 + 0) * 64 + b] = xv.x;
            sx2[(f0 + 1) * 64 + b] = xv.y;
            sx2[(f0 + 2) * 64 + b] = xv.z;
            sx2[(f0 + 3) * 64 + b] = xv.w;
        }
        __syncthreads();

        unsigned long long a0 = bp, a1 = bp;   // (b0,b0+1), (b0+2,b0+3)

        // ---- input projection (K=64) ----
        #pragma unroll 8
        for (int f = 0; f < FF; ++f) {
            unsigned long long wv = wxrow[f];
            ulonglong2 xv = *(const ulonglong2*)(sx2 + f * 64 + b0);
            a0 = fma2(xv.x, wv, a0);
            a1 = fma2(xv.y, wv, a1);
        }

        // ---- recurrent projection (K=512), double-buffered chunks ----
        if (t > 0) {
            const float* hsrc = g_hsT + (size_t)(t - 1) * UU * BB;
            {
                const float4* src = (const float4*)hsrc;
                for (int i = tid; i < (KT * BB) / 4; i += NTHR)
                    cp_async16(sh + i * 4, src + i);
                CP_COMMIT();
            }
            #pragma unroll
            for (int ch = 0; ch < UU / KT; ++ch) {
                if (ch + 1 < UU / KT) {
                    float* dst = sh + ((ch + 1) & 1) * KT * BB;
                    const float4* src = (const float4*)(hsrc + (ch + 1) * KT * BB);
                    for (int i = tid; i < (KT * BB) / 4; i += NTHR)
                        cp_async16(dst + i * 4, src + i);
                    CP_COMMIT();
                    CP_WAIT1();
                } else {
                    CP_WAIT0();
                }
                __syncthreads();

                const float* hb = sh + (ch & 1) * KT * BB;
                const unsigned long long* wc = wrow + ch * KT;
                #pragma unroll 8
                for (int k = 0; k < KT; ++k) {
                    unsigned long long wv = wc[k];
                    ulonglong2 hv = *(const ulonglong2*)(hb + k * 64 + b0);
                    a0 = fma2(hv.x, wv, a0);
                    a1 = fma2(hv.y, wv, a1);
                }
                __syncthreads();
            }
        }

        // ---- exchange gates via smem: sg[c*68 + b] ----
        *(ulonglong2*)(sg + c * 68 + b0) = make_ulonglong2(a0, a1);
        __syncthreads();

        // ---- pointwise: thread owns (unit pj, batch pb) ----
        {
            float iv = sg[(0 * 4 + pj) * 68 + pb];
            float fv = sg[(1 * 4 + pj) * 68 + pb];
            float gv = sg[(2 * 4 + pj) * 68 + pb];
            float ov = sg[(3 * 4 + pj) * 68 + pb];
            creg = sigmoidf_(fv) * creg + sigmoidf_(iv) * tanhf(gv);
            float hval = sigmoidf_(ov) * tanhf(creg);
            g_hsT[((size_t)t * UU + u0 + pj) * 64 + pb] = hval;
        }

        grid_barrier();
    }
}

// ---------------------------------------------------------------------------
// Output: y[b,t] = sigmoid(coef[t] * <h_bt, out_W> + shift[t]*sumW + out_b)
// ---------------------------------------------------------------------------
__global__ void out_kernel(const float* __restrict__ outW,
                           const float* __restrict__ outb,
                           float* __restrict__ y)
{
    int t  = blockIdx.x;
    int b  = threadIdx.x & 63;
    int ug = threadIdx.x >> 6;   // 0..3
    float s = 0.f;
    const float* base = g_hsT + (size_t)t * UU * BB;
    #pragma unroll 4
    for (int u = ug * 128; u < ug * 128 + 128; ++u)
        s += base[(size_t)u * 64 + b] * outW[u];
    __shared__ float red[4][64];
    red[ug][b] = s;
    __syncthreads();
    if (ug == 0) {
        float v = red[0][b] + red[1][b] + red[2][b] + red[3][b];
        v = g_coef[t] * v + g_shift[t] * g_sumW + outb[0];
        y[b * TT + t] = 1.f / (1.f + expf(-v));
    }
}

// ---------------------------------------------------------------------------
extern "C" void kernel_launch(void* const* d_in, const int* in_sizes, int n_in,
                              void* d_out, int out_size)
{
    (void)in_sizes; (void)n_in; (void)out_size;
    const float* inputs = (const float*)d_in[0];
    const float* kernel = (const float*)d_in[1];
    const float* rec    = (const float*)d_in[2];
    const float* bias   = (const float*)d_in[3];
    const float* attW   = (const float*)d_in[4];
    const float* attb   = (const float*)d_in[5];
    const float* outW   = (const float*)d_in[6];
    const float* outb   = (const float*)d_in[7];
    float* y = (float*)d_out;

    static int smem_set = 0;
    size_t smem_bytes = SMEM_FLOATS * sizeof(float);   // ~156.5 KB
    if (!smem_set) {
        cudaFuncSetAttribute(lstm_persist,
                             cudaFuncAttributeMaxDynamicSharedMemorySize,
                             (int)smem_bytes);
        smem_set = 1;
    }

    prep_kernel<<<TT + 1, 256>>>(attW, attb, outW);
    lstm_persist<<<NBLK, NTHR, smem_bytes>>>(inputs, kernel, rec, bias);
    out_kernel<<<TT, 256>>>(outW, outb, y);
}

// round 5
// speedup vs baseline: 1.1883x; 1.1883x over previous
#include <cuda_runtime.h>
#include <math.h>

#define BB 64
#define TT 256
#define FF 64
#define UU 512
#define GG 2048      // 4*UU
#define NBLK 128
#define NTHR 256
#define CU 4         // units per block
#define NC 16        // gate-columns per block (4 gates x 4 units)
#define KT 128       // k-chunk for h staging
#define WS 513       // rec dup-weight row stride (float2 units, odd)
#define WXS 65       // x dup-weight row stride (float2 units)

// ---- static device scratch (no cudaMalloc anywhere) ----
__device__ float g_hsT[(size_t)TT * UU * BB]; // all h: [(t*512+u)*64 + b]
__device__ float g_coef[TT];
__device__ float g_shift[TT];
__device__ float g_sumW;
__device__ unsigned g_cnt = 0;
__device__ volatile unsigned g_gen = 0;       // monotonic across launches

__device__ __forceinline__ float sigmoidf_(float x) { return 1.f / (1.f + expf(-x)); }

// packed fp32x2 FMA (Blackwell)
__device__ __forceinline__ unsigned long long fma2(unsigned long long a,
                                                   unsigned long long b,
                                                   unsigned long long c) {
    unsigned long long d;
    asm("fma.rn.f32x2 %0, %1, %2, %3;" : "=l"(d) : "l"(a), "l"(b), "l"(c));
    return d;
}
__device__ __forceinline__ unsigned long long pack2(float v) {
    unsigned long long p;
    unsigned u = __float_as_uint(v);
    asm("mov.b64 %0, {%1, %1};" : "=l"(p) : "r"(u));
    return p;
}

__device__ __forceinline__ void cp_async16(float* smem_dst, const void* gmem_src) {
    unsigned s = (unsigned)__cvta_generic_to_shared(smem_dst);
    asm volatile("cp.async.cg.shared.global [%0], [%1], 16;\n" :: "r"(s), "l"(gmem_src));
}
#define CP_COMMIT() asm volatile("cp.async.commit_group;\n" ::: "memory")
#define CP_WAIT1()  asm volatile("cp.async.wait_group 1;\n" ::: "memory")
#define CP_WAIT0()  asm volatile("cp.async.wait_group 0;\n" ::: "memory")

__device__ __forceinline__ void grid_barrier() {
    __threadfence();
    __syncthreads();
    if (threadIdx.x == 0) {
        unsigned gen = g_gen;
        if (atomicAdd(&g_cnt, 1u) == (unsigned)(NBLK - 1)) {
            g_cnt = 0u;
            __threadfence();
            g_gen = gen + 1u;
        } else {
            while (g_gen == gen) { }
        }
    }
    __syncthreads();
}

// no-op pad so ncu's fixed capture slot (-s 5) lands on lstm_persist
__global__ void pad_kernel() {}

// ---------------------------------------------------------------------------
// prep (parallel): block t<TT computes coef/shift; block TT reduces out_W.
// ---------------------------------------------------------------------------
__global__ void prep_kernel(const float* __restrict__ attW,
                            const float* __restrict__ attb,
                            const float* __restrict__ outW)
{
    __shared__ float red[256];
    int tid = threadIdx.x;
    if (blockIdx.x < TT) {
        int t = blockIdx.x;
        float s = 0.f;
        for (int j = tid; j < t; j += 256) s += attW[t * TT + j];
        red[tid] = s;
        __syncthreads();
        for (int off = 128; off > 0; off >>= 1) {
            if (tid < off) red[tid] += red[tid + off];
            __syncthreads();
        }
        if (tid == 0) {
            g_coef[t]  = (t == 0) ? 1.f : red[0];
            g_shift[t] = (t == 0) ? 0.f : attb[t];
        }
    } else {
        red[tid] = outW[tid] + outW[tid + 256];
        __syncthreads();
        for (int off = 128; off > 0; off >>= 1) {
            if (tid < off) red[tid] += red[tid + off];
            __syncthreads();
        }
        if (tid == 0) g_sumW = red[0];
    }
}

// ---------------------------------------------------------------------------
// Persistent LSTM. 128 blocks, 256 threads (2 warps/SMSP via split-K).
// Block owns 4 units (16 gate cols).
// Thread tile: 2 cols x 4 batches (4 indep f32x2 chains), k-half kh of each
// chunk. Duplicated f32x2 weights in smem -> no packing MOVs in inner loop.
// ---------------------------------------------------------------------------
// smem (floats):
//   sh   [2][KT*64]       = 16384
//   sWd  [16][513 f32x2]  = 16416
//   sWxd [16][65 f32x2]   =  2080
//   sx2  [64][64]         =  4096
//   sg   [2][16][68]      =  2176
#define OFF_SH   0
#define OFF_SW   (2 * KT * BB)
#define OFF_SWX  (OFF_SW + NC * WS * 2)
#define OFF_SX   (OFF_SWX + NC * WXS * 2)
#define OFF_SG   (OFF_SX + FF * BB)
#define SMEM_FLOATS (OFF_SG + 2 * NC * 68)

__global__ void __launch_bounds__(NTHR, 1)
lstm_persist(const float* __restrict__ x,     // (B,T,F)
             const float* __restrict__ Wk,    // (F,4U)
             const float* __restrict__ Rk,    // (U,4U)
             const float* __restrict__ bias)  // (4U)
{
    extern __shared__ float smem[];
    float* sh   = smem + OFF_SH;
    float* sWd  = smem + OFF_SW;
    float* sWxd = smem + OFF_SWX;
    float* sx2  = smem + OFF_SX;
    float* sg   = smem + OFF_SG;

    const int tid = threadIdx.x;
    const int bid = blockIdx.x;
    const int u0  = bid * CU;

    // ---- one-time weight staging, duplicated halves ----
    for (int idx = tid; idx < UU * NC; idx += NTHR) {
        int k = idx >> 4, c = idx & 15;
        int gcol = (c >> 2) * UU + u0 + (c & 3);
        float w = Rk[(size_t)k * GG + gcol];
        ((float2*)sWd)[c * WS + k] = make_float2(w, w);
    }
    for (int idx = tid; idx < FF * NC; idx += NTHR) {
        int f = idx >> 4, c = idx & 15;
        int gcol = (c >> 2) * UU + u0 + (c & 3);
        float w = Wk[(size_t)f * GG + gcol];
        ((float2*)sWxd)[c * WXS + f] = make_float2(w, w);
    }

    // GEMM identity: k-half kh, cols {cg, cg+8}, batches [b0, b0+4)
    const int kh   = tid >> 7;            // 0/1
    const int gtid = tid & 127;
    const int cg   = gtid & 7;
    const int b0   = ((gtid >> 3) & 15) << 2;
    const int c0 = cg, c1 = cg + 8;
    const unsigned long long bp0 =
        (kh == 0) ? pack2(bias[(c0 >> 2) * UU + u0 + (c0 & 3)]) : 0ull;
    const unsigned long long bp1 =
        (kh == 0) ? pack2(bias[(c1 >> 2) * UU + u0 + (c1 & 3)]) : 0ull;

    const unsigned long long* w0row = (const unsigned long long*)((float2*)sWd + c0 * WS);
    const unsigned long long* w1row = (const unsigned long long*)((float2*)sWd + c1 * WS);
    const unsigned long long* wx0   = (const unsigned long long*)((float2*)sWxd + c0 * WXS);
    const unsigned long long* wx1   = (const unsigned long long*)((float2*)sWxd + c1 * WXS);

    // pointwise identity: unit pj, batch pb
    const int pj = tid >> 6;   // 0..3
    const int pb = tid & 63;
    float creg = 0.f;

    __syncthreads();

    for (int t = 0; t < TT; ++t) {
        // ---- stage x_t transposed: sx2[f*64 + b] ----
        for (int i = tid; i < (BB * FF) / 4; i += NTHR) {
            int b  = i & 63;
            int f0 = (i >> 6) << 2;
            float4 xv = *(const float4*)(x + ((size_t)b * TT + t) * FF + f0);
            sx2[(f0 + 0) * 64 + b] = xv.x;
            sx2[(f0 + 1) * 64 + b] = xv.y;
            sx2[(f0 + 2) * 64 + b] = xv.z;
            sx2[(f0 + 3) * 64 + b] = xv.w;
        }
        __syncthreads();

        unsigned long long a00 = bp0, a01 = bp0;  // col c0, pairs (b0,b0+1),(b0+2,b0+3)
        unsigned long long a10 = bp1, a11 = bp1;  // col c1

        // ---- input projection: this group's half of K=64 ----
        {
            const int fbase = kh * 32;
            #pragma unroll 8
            for (int f = 0; f < 32; ++f) {
                unsigned long long w0 = wx0[fbase + f];
                unsigned long long w1 = wx1[fbase + f];
                ulonglong2 hv = *(const ulonglong2*)(sx2 + (fbase + f) * 64 + b0);
                a00 = fma2(hv.x, w0, a00); a01 = fma2(hv.y, w0, a01);
                a10 = fma2(hv.x, w1, a10); a11 = fma2(hv.y, w1, a11);
            }
        }

        // ---- recurrent projection (K=512), double-buffered chunks,
        //      each group computes its k-half of every chunk ----
        if (t > 0) {
            const float* hsrc = g_hsT + (size_t)(t - 1) * UU * BB;
            {
                const float4* src = (const float4*)hsrc;
                for (int i = tid; i < (KT * BB) / 4; i += NTHR)
                    cp_async16(sh + i * 4, src + i);
                CP_COMMIT();
            }
            #pragma unroll
            for (int ch = 0; ch < UU / KT; ++ch) {
                if (ch + 1 < UU / KT) {
                    float* dst = sh + ((ch + 1) & 1) * KT * BB;
                    const float4* src = (const float4*)(hsrc + (ch + 1) * KT * BB);
                    for (int i = tid; i < (KT * BB) / 4; i += NTHR)
                        cp_async16(dst + i * 4, src + i);
                    CP_COMMIT();
                    CP_WAIT1();
                } else {
                    CP_WAIT0();
                }
                __syncthreads();

                const float* hb = sh + (ch & 1) * KT * BB + kh * (KT / 2) * BB;
                const unsigned long long* w0p = w0row + ch * KT + kh * (KT / 2);
                const unsigned long long* w1p = w1row + ch * KT + kh * (KT / 2);
                #pragma unroll 8
                for (int k = 0; k < KT / 2; ++k) {
                    unsigned long long w0 = w0p[k];
                    unsigned long long w1 = w1p[k];
                    ulonglong2 hv = *(const ulonglong2*)(hb + k * 64 + b0);
                    a00 = fma2(hv.x, w0, a00); a01 = fma2(hv.y, w0, a01);
                    a10 = fma2(hv.x, w1, a10); a11 = fma2(hv.y, w1, a11);
                }
                __syncthreads();
            }
        }

        // ---- write partial gate sums: sg[kh][c][b] ----
        float* sgk = sg + kh * NC * 68;
        *(ulonglong2*)(sgk + c0 * 68 + b0) = make_ulonglong2(a00, a01);
        *(ulonglong2*)(sgk + c1 * 68 + b0) = make_ulonglong2(a10, a11);
        __syncthreads();

        // ---- pointwise: thread owns (unit pj, batch pb); sum both k-halves ----
        {
            const float* s0 = sg;
            const float* s1 = sg + NC * 68;
            float iv = s0[(0 * 4 + pj) * 68 + pb] + s1[(0 * 4 + pj) * 68 + pb];
            float fv = s0[(1 * 4 + pj) * 68 + pb] + s1[(1 * 4 + pj) * 68 + pb];
            float gv = s0[(2 * 4 + pj) * 68 + pb] + s1[(2 * 4 + pj) * 68 + pb];
            float ov = s0[(3 * 4 + pj) * 68 + pb] + s1[(3 * 4 + pj) * 68 + pb];
            creg = sigmoidf_(fv) * creg + sigmoidf_(iv) * tanhf(gv);
            float hval = sigmoidf_(ov) * tanhf(creg);
            g_hsT[((size_t)t * UU + u0 + pj) * 64 + pb] = hval;
        }

        grid_barrier();
    }
}

// ---------------------------------------------------------------------------
// Output: y[b,t] = sigmoid(coef[t] * <h_bt, out_W> + shift[t]*sumW + out_b)
// ---------------------------------------------------------------------------
__global__ void out_kernel(const float* __restrict__ outW,
                           const float* __restrict__ outb,
                           float* __restrict__ y)
{
    int t  = blockIdx.x;
    int b  = threadIdx.x & 63;
    int ug = threadIdx.x >> 6;   // 0..3
    float s = 0.f;
    const float* base = g_hsT + (size_t)t * UU * BB;
    #pragma unroll 4
    for (int u = ug * 128; u < ug * 128 + 128; ++u)
        s += base[(size_t)u * 64 + b] * outW[u];
    __shared__ float red[4][64];
    red[ug][b] = s;
    __syncthreads();
    if (ug == 0) {
        float v = red[0][b] + red[1][b] + red[2][b] + red[3][b];
        v = g_coef[t] * v + g_shift[t] * g_sumW + outb[0];
        y[b * TT + t] = 1.f / (1.f + expf(-v));
    }
}

// ---------------------------------------------------------------------------
extern "C" void kernel_launch(void* const* d_in, const int* in_sizes, int n_in,
                              void* d_out, int out_size)
{
    (void)in_sizes; (void)n_in; (void)out_size;
    const float* inputs = (const float*)d_in[0];
    const float* kernel = (const float*)d_in[1];
    const float* rec    = (const float*)d_in[2];
    const float* bias   = (const float*)d_in[3];
    const float* attW   = (const float*)d_in[4];
    const float* attb   = (const float*)d_in[5];
    const float* outW   = (const float*)d_in[6];
    const float* outb   = (const float*)d_in[7];
    float* y = (float*)d_out;

    static int smem_set = 0;
    size_t smem_bytes = SMEM_FLOATS * sizeof(float);   // ~160.8 KB
    if (!smem_set) {
        cudaFuncSetAttribute(lstm_persist,
                             cudaFuncAttributeMaxDynamicSharedMemorySize,
                             (int)smem_bytes);
        smem_set = 1;
    }

    // two pads so lstm_persist lands on ncu's capture slot (-s 5, with the
    // 2 harness launches ahead of ours)
    pad_kernel<<<1, 32>>>();
    pad_kernel<<<1, 32>>>();
    prep_kernel<<<TT + 1, 256>>>(attW, attb, outW);
    lstm_persist<<<NBLK, NTHR, smem_bytes>>>(inputs, kernel, rec, bias);
    out_kernel<<<TT, 256>>>(outW, outb, y);
}